// round 16
// baseline (speedup 1.0000x reference)
#include <cuda_runtime.h>
#include <math.h>

// Problem dims
#define Tt 1024
#define Bb 64
#define Ii 256
#define Hh 512
#define Oo 128

// Scan grid: 128 CTAs, each owns 16 batches x 16 cols of BOTH layers.
// Batch groups of 32 CTAs (same 16 batches) exchange h; groups are independent.
#define G_CTAS 128
#define RNN_THREADS 256

// ---------------- device scratch (no runtime allocation allowed) ----------------
__device__ float g_xproj[(size_t)Tt * Bb * Hh];   // x@W_ih0^T + b_ih0 + b_hh0, [t][b][h]
__device__ float g_h0[4][Bb * Hh];                // quad-buffered layer-0 hidden
__device__ float g_h1[4][Bb * Hh];                // quad-buffered layer-1 hidden
__device__ unsigned g_flag0[G_CTAS * 32];         // L0 pipeline flags (128B padded)
__device__ unsigned g_flag1[G_CTAS * 32];         // L1 pipeline flags

// ---------------- packed f32x2 helpers ----------------
#define FMA2(acc, a, b) \
    asm("fma.rn.f32x2 %0, %1, %2, %0;" : "+l"(acc) : "l"(a), "l"(b))

__device__ __forceinline__ float f2sum(unsigned long long u) {
    float lo, hi;
    asm("mov.b64 {%0,%1}, %2;" : "=f"(lo), "=f"(hi) : "l"(u));
    return lo + hi;
}

// 16B L2-coherent global load as two packed f32x2 operands
__device__ __forceinline__ void ldcg2x64(const float* g,
                                         unsigned long long& a, unsigned long long& b) {
    asm volatile("ld.global.cg.v2.u64 {%0,%1}, [%2];" : "=l"(a), "=l"(b) : "l"(g));
}

// ---------------- cp.async (L2-direct; coherence-safe across SMs) ----------------
__device__ __forceinline__ void cpa16(unsigned s, const float* g) {
    asm volatile("cp.async.cg.shared.global [%0], [%1], 16;" :: "r"(s), "l"(g));
}

__device__ __forceinline__ unsigned ld_acq(const unsigned* p) {
    unsigned v;
    asm volatile("ld.acquire.gpu.u32 %0, [%1];" : "=r"(v) : "l"(p) : "memory");
    return v;
}
__device__ __forceinline__ void st_rel(unsigned* p, unsigned v) {
    asm volatile("st.relaxed.gpu.u32 [%0], %1;" :: "l"(p), "r"(v) : "memory");
}
__device__ __forceinline__ void named_bar(int id) {
    asm volatile("bar.sync %0, 128;" :: "r"(id) : "memory");
}

// Multi-value butterfly allreduce: on return v[0] holds, for lane L, the full
// 32-lane sum of original v[L]. 31 shfls total.
__device__ __forceinline__ void butterfly32(float (&v)[32], int ln) {
    #pragma unroll
    for (int m = 16; m >= 1; m >>= 1) {
        #pragma unroll
        for (int i = 0; i < m; ++i) {
            float a = v[i], b = v[i + m];
            float send = (ln & m) ? a : b;
            float recv = __shfl_xor_sync(0xffffffffu, send, m);
            v[i] = (ln & m) ? (b + recv) : (a + recv);
        }
    }
}

// =================================================================================
// Kernel 1: xproj[t][b][j] = sum_i x[b][t][i] * W_ih0[j][i] + b_ih0[j] + b_hh0[j]
// =================================================================================
__global__ void __launch_bounds__(256) xproj_kernel(
    const float* __restrict__ x, const float* __restrict__ W,
    const float* __restrict__ bih, const float* __restrict__ bhh)
{
    __shared__ float xs[64 * 68];
    __shared__ float ws[64 * 68];

    const int t   = blockIdx.y;
    const int n0  = blockIdx.x * 64;
    const int tid = threadIdx.x;
    const int tx  = tid & 15;
    const int ty  = tid >> 4;
    const int mi0 = ty * 4;
    const int ni0 = tx * 4;

    float acc[4][4] = {};

    for (int kc = 0; kc < 4; ++kc) {
        const int k0 = kc * 64;
        for (int idx = tid; idx < 1024; idx += 256) {
            int b  = idx >> 4;
            int c4 = idx & 15;
            float4 v = *reinterpret_cast<const float4*>(
                x + ((size_t)b * Tt + t) * Ii + k0 + c4 * 4);
            *reinterpret_cast<float4*>(xs + b * 68 + c4 * 4) = v;
        }
        for (int idx = tid; idx < 1024; idx += 256) {
            int nl = idx >> 4;
            int c4 = idx & 15;
            float4 v = *reinterpret_cast<const float4*>(
                W + (size_t)(n0 + nl) * Ii + k0 + c4 * 4);
            int k = c4 * 4;
            ws[(k + 0) * 68 + nl] = v.x;
            ws[(k + 1) * 68 + nl] = v.y;
            ws[(k + 2) * 68 + nl] = v.z;
            ws[(k + 3) * 68 + nl] = v.w;
        }
        __syncthreads();
        #pragma unroll 8
        for (int k = 0; k < 64; ++k) {
            float4 wv = *reinterpret_cast<const float4*>(ws + k * 68 + ni0);
            float x0 = xs[(mi0 + 0) * 68 + k];
            float x1 = xs[(mi0 + 1) * 68 + k];
            float x2 = xs[(mi0 + 2) * 68 + k];
            float x3 = xs[(mi0 + 3) * 68 + k];
            acc[0][0] += x0 * wv.x; acc[0][1] += x0 * wv.y; acc[0][2] += x0 * wv.z; acc[0][3] += x0 * wv.w;
            acc[1][0] += x1 * wv.x; acc[1][1] += x1 * wv.y; acc[1][2] += x1 * wv.z; acc[1][3] += x1 * wv.w;
            acc[2][0] += x2 * wv.x; acc[2][1] += x2 * wv.y; acc[2][2] += x2 * wv.z; acc[2][3] += x2 * wv.w;
            acc[3][0] += x3 * wv.x; acc[3][1] += x3 * wv.y; acc[3][2] += x3 * wv.z; acc[3][3] += x3 * wv.w;
        }
        __syncthreads();
    }

    float4 bias;
    bias.x = bih[n0 + ni0 + 0] + bhh[n0 + ni0 + 0];
    bias.y = bih[n0 + ni0 + 1] + bhh[n0 + ni0 + 1];
    bias.z = bih[n0 + ni0 + 2] + bhh[n0 + ni0 + 2];
    bias.w = bih[n0 + ni0 + 3] + bhh[n0 + ni0 + 3];
    #pragma unroll
    for (int i = 0; i < 4; ++i) {
        float4 o;
        o.x = acc[i][0] + bias.x;
        o.y = acc[i][1] + bias.y;
        o.z = acc[i][2] + bias.z;
        o.w = acc[i][3] + bias.w;
        *reinterpret_cast<float4*>(
            g_xproj + ((size_t)t * Bb + (mi0 + i)) * Hh + n0 + ni0) = o;
    }
}

// =================================================================================
// Kernel 2: persistent scan, two elastically decoupled pipelines (depth-4 buffers).
//   L0 (warps 4-7, flags0): h0(p) = tanh(xproj[p-1] + h0(p-1)@W_hh0^T)
//     reads h0 tile DIRECTLY from L2 (no smem stage) -> 2 named bars/step.
//     polls: flags0 >= base0+p (h0(p-1) ready), flags1 >= base1+p-3 (slot safety).
//   L1 (warps 0-3, flags1): h1(p) = tanh(h0(p)@W_ih1^T + h1(p-1)@W_hh1^T + b)
//     cp.async staging (has slack; throughput path).
//     polls: flags0 >= base0+1+p (h0(p)), flags1 >= base1+p (h1(p-1) + slot safety).
// flag = base + 1 + s  <=>  h(s) globally visible. Group = 32 CTAs, same batches.
// =================================================================================
extern __shared__ float smf[];

__global__ void __launch_bounds__(RNN_THREADS, 1) rnn_kernel(
    const float* __restrict__ h_init,
    const float* __restrict__ W_hh0,
    const float* __restrict__ W_ih1, const float* __restrict__ b_ih1,
    const float* __restrict__ W_hh1, const float* __restrict__ b_hh1)
{
    const int tid = threadIdx.x;
    const int cta = blockIdx.x;
    const int ln  = tid & 31;
    const int wl  = (tid >> 5) & 3;      // warp index within half
    const bool isL0 = (tid >= 128);      // hi-wid warps: latency-critical h0 chain
    const int tpr = tid & 127;           // thread rank within half
    const int group = cta >> 5;          // batch group (4 groups of 32 CTAs)
    const int B0  = group * 16;
    const int C0  = (cta & 31) * 16;
    const int lb  = (wl & 1) * 8;        // warp local batch base
    const int cw  = (wl >> 1) * 8;       // warp local col base

    // SMEM: W0 | Wi1 | Wh1 | hsB (L1: h0 stage) | hsC (L1: h1 stage)
    float* W0  = smf;
    float* Wi1 = smf + 8192;
    float* Wh1 = smf + 16384;
    float* hsB = smf + 24576;
    float* hsC = smf + 32768;

    const unsigned base0 = g_flag0[cta * 32];   // uniform across CTAs between launches
    const unsigned base1 = g_flag1[cta * 32];

    // ---- load weight slices (K contiguous per col) ----
    {
        float4* d0 = reinterpret_cast<float4*>(W0);
        float4* d1 = reinterpret_cast<float4*>(Wi1);
        float4* d2 = reinterpret_cast<float4*>(Wh1);
        for (int i = tid; i < 16 * 128; i += RNN_THREADS) {
            int c = i >> 7, k4 = i & 127;
            size_t go = (size_t)(C0 + c) * Hh + k4 * 4;
            d0[i] = *reinterpret_cast<const float4*>(W_hh0 + go);
            d1[i] = *reinterpret_cast<const float4*>(W_ih1 + go);
            d2[i] = *reinterpret_cast<const float4*>(W_hh1 + go);
        }
    }
    // ---- init state: members split their group's 16x512 slice (slot 0) ----
    {
        float4* h0d = reinterpret_cast<float4*>(g_h0[0] + (size_t)B0 * Hh);
        float4* h1d = reinterpret_cast<float4*>(g_h1[0] + (size_t)B0 * Hh);
        const float4* s0 = reinterpret_cast<const float4*>(h_init + (size_t)B0 * Hh);
        const float4* s1 = reinterpret_cast<const float4*>(h_init + (size_t)(Bb + B0) * Hh);
        int mem = cta & 31;                        // 2048 float4 / 32 members = 64 each
        if (tid < 64) {
            int i = mem * 64 + tid;
            h0d[i] = s0[i];
            h1d[i] = s1[i];
        }
    }
    __syncthreads();
    if (tid == 0) {
        __threadfence();
        st_rel(&g_flag0[cta * 32], base0 + 1);   // h0(0) visible
        st_rel(&g_flag1[cta * 32], base1 + 1);   // h1(0) visible
    }

    // per-lane output mapping (flat acc idx = b*8+c)
    const int ob0 = lb + (ln >> 3);
    const int ob1 = ob0 + 4;
    const int gc  = C0 + cw + (ln & 7);

    if (isL0) {
        // ================= L0 pipeline: warps 4-7, named barrier 1 =================
        const float* xpa = g_xproj + (size_t)(B0 + ob0) * Hh + gc;
        const float* xpb = g_xproj + (size_t)(B0 + ob1) * Hh + gc;

        for (int p = 1; p <= Tt; ++p) {
            if (tpr < 32) {
                const unsigned* f0 = &g_flag0[(group * 32 + tpr) * 32];
                const unsigned* f1 = &g_flag1[(group * 32 + tpr) * 32];
                unsigned t0 = base0 + p;          // h0(p-1) ready everywhere
                unsigned t1 = base1 + p - 3;      // L1 done step p-4 (slot p&3 safe)
                while ((int)(ld_acq(f0) - t0) < 0 || (int)(ld_acq(f1) - t1) < 0) { }
            }
            named_bar(1);

            const float* h0prev = g_h0[(p - 1) & 3];
            float*       h0out  = g_h0[p & 3];

            const size_t toff = (size_t)(p - 1) * (Bb * Hh);
            float px0 = __ldcg(xpa + toff);
            float px1 = __ldcg(xpb + toff);

            unsigned long long acc[64];
            #pragma unroll
            for (int i = 0; i < 64; ++i) acc[i] = 0ull;

            // h rows read directly from L2 (coherent); W from resident smem
            #pragma unroll
            for (int m = 0; m < 4; ++m) {
                const int k = m * 128 + ln * 4;
                unsigned long long hx[8], hy[8];
                #pragma unroll
                for (int b = 0; b < 8; ++b)
                    ldcg2x64(h0prev + (size_t)(B0 + lb + b) * Hh + k, hx[b], hy[b]);
                #pragma unroll
                for (int c = 0; c < 8; ++c) {
                    ulonglong2 w2 = *reinterpret_cast<const ulonglong2*>(W0 + (cw + c) * 512 + k);
                    #pragma unroll
                    for (int b = 0; b < 8; ++b) {
                        FMA2(acc[b * 8 + c], hx[b], w2.x);
                        FMA2(acc[b * 8 + c], hy[b], w2.y);
                    }
                }
            }

            float v[32];
            #pragma unroll
            for (int i = 0; i < 32; ++i) v[i] = f2sum(acc[i]);
            butterfly32(v, ln);
            float out0 = v[0];
            #pragma unroll
            for (int i = 0; i < 32; ++i) v[i] = f2sum(acc[32 + i]);
            butterfly32(v, ln);
            float out1 = v[0];

            h0out[(size_t)(B0 + ob0) * Hh + gc] = tanhf(out0 + px0);
            h0out[(size_t)(B0 + ob1) * Hh + gc] = tanhf(out1 + px1);

            named_bar(1);
            if (tpr == 0) {
                __threadfence();
                st_rel(&g_flag0[cta * 32], base0 + 1 + p);
            }
        }
    } else {
        // ================= L1 pipeline: warps 0-3, named barrier 2 =================
        const float bias1 = b_ih1[gc] + b_hh1[gc];
        const unsigned hsBu = (unsigned)__cvta_generic_to_shared(hsB);
        const unsigned hsCu = (unsigned)__cvta_generic_to_shared(hsC);

        for (int p = 1; p <= Tt; ++p) {
            if (tpr < 32) {
                const unsigned* f0 = &g_flag0[(group * 32 + tpr) * 32];
                const unsigned* f1 = &g_flag1[(group * 32 + tpr) * 32];
                unsigned t0 = base0 + 1 + p;    // h0(p) ready
                unsigned t1 = base1 + p;        // h1(p-1) ready (+ slot safety)
                while ((int)(ld_acq(f0) - t0) < 0 || (int)(ld_acq(f1) - t1) < 0) { }
            }
            named_bar(2);

            const float* h0cur  = g_h0[p & 3];         // h0(p)
            const float* h1prev = g_h1[(p - 1) & 3];   // h1(p-1)
            float*       h1out  = g_h1[p & 3];         // h1(p)
            #pragma unroll
            for (int q = 0; q < 16; ++q) {
                int idx = q * 128 + tpr;
                int b = idx >> 7, k4 = idx & 127;
                cpa16(hsBu + (unsigned)(b * 512 + k4 * 4) * 4u,
                      h0cur + (size_t)(B0 + b) * Hh + k4 * 4);
                cpa16(hsCu + (unsigned)(b * 512 + k4 * 4) * 4u,
                      h1prev + (size_t)(B0 + b) * Hh + k4 * 4);
            }
            asm volatile("cp.async.commit_group;");
            asm volatile("cp.async.wait_group 0;" ::: "memory");
            named_bar(2);

            unsigned long long acc[64];
            #pragma unroll
            for (int i = 0; i < 64; ++i) acc[i] = 0ull;

            #pragma unroll
            for (int m = 0; m < 4; ++m) {
                const int k = m * 128 + ln * 4;
                ulonglong2 h2[8];
                #pragma unroll
                for (int b = 0; b < 8; ++b)
                    h2[b] = *reinterpret_cast<const ulonglong2*>(hsB + (lb + b) * 512 + k);
                #pragma unroll
                for (int c = 0; c < 8; ++c) {
                    ulonglong2 w2 = *reinterpret_cast<const ulonglong2*>(Wi1 + (cw + c) * 512 + k);
                    #pragma unroll
                    for (int b = 0; b < 8; ++b) {
                        FMA2(acc[b * 8 + c], h2[b].x, w2.x);
                        FMA2(acc[b * 8 + c], h2[b].y, w2.y);
                    }
                }
            }
            #pragma unroll
            for (int m = 0; m < 4; ++m) {
                const int k = m * 128 + ln * 4;
                ulonglong2 h2[8];
                #pragma unroll
                for (int b = 0; b < 8; ++b)
                    h2[b] = *reinterpret_cast<const ulonglong2*>(hsC + (lb + b) * 512 + k);
                #pragma unroll
                for (int c = 0; c < 8; ++c) {
                    ulonglong2 w2 = *reinterpret_cast<const ulonglong2*>(Wh1 + (cw + c) * 512 + k);
                    #pragma unroll
                    for (int b = 0; b < 8; ++b) {
                        FMA2(acc[b * 8 + c], h2[b].x, w2.x);
                        FMA2(acc[b * 8 + c], h2[b].y, w2.y);
                    }
                }
            }

            float v[32];
            #pragma unroll
            for (int i = 0; i < 32; ++i) v[i] = f2sum(acc[i]);
            butterfly32(v, ln);
            float out0 = v[0];
            #pragma unroll
            for (int i = 0; i < 32; ++i) v[i] = f2sum(acc[32 + i]);
            butterfly32(v, ln);
            float out1 = v[0];

            h1out[(size_t)(B0 + ob0) * Hh + gc] = tanhf(out0 + bias1);
            h1out[(size_t)(B0 + ob1) * Hh + gc] = tanhf(out1 + bias1);

            named_bar(2);
            if (tpr == 0) {
                __threadfence();
                st_rel(&g_flag1[cta * 32], base1 + 1 + p);
            }
        }
    }
}

// =================================================================================
// Kernel 3: out[b][o] = h1(1024)[b] . W_out[o] + b_out[o]   (1024 & 3 == slot 0)
// =================================================================================
__global__ void __launch_bounds__(128) head_kernel(
    const float* __restrict__ W_out, const float* __restrict__ b_out,
    float* __restrict__ out)
{
    const int b = blockIdx.x;
    const int o = threadIdx.x;
    const float* h = g_h1[0] + b * Hh;
    const float* wv = W_out + (size_t)o * Hh;
    float acc = 0.f;
    #pragma unroll 8
    for (int k = 0; k < Hh; k += 4) {
        float4 hv = *reinterpret_cast<const float4*>(h + k);
        float4 wr = *reinterpret_cast<const float4*>(wv + k);
        acc += hv.x * wr.x + hv.y * wr.y + hv.z * wr.z + hv.w * wr.w;
    }
    out[b * Oo + o] = acc + b_out[o];
}

// =================================================================================
extern "C" void kernel_launch(void* const* d_in, const int* in_sizes, int n_in,
                              void* d_out, int out_size)
{
    (void)in_sizes; (void)n_in; (void)out_size;
    const float* x      = (const float*)d_in[0];
    const float* h0     = (const float*)d_in[1];
    const float* W_ih0  = (const float*)d_in[2];
    const float* b_ih0  = (const float*)d_in[3];
    const float* W_hh0  = (const float*)d_in[4];
    const float* b_hh0  = (const float*)d_in[5];
    const float* W_ih1  = (const float*)d_in[6];
    const float* b_ih1  = (const float*)d_in[7];
    const float* W_hh1  = (const float*)d_in[8];
    const float* b_hh1  = (const float*)d_in[9];
    const float* W_out  = (const float*)d_in[10];
    const float* b_out  = (const float*)d_in[11];
    float* out = (float*)d_out;

    // SMEM: 5 x (16x512 floats) = 40960 floats = 160 KB
    static int smem_set = 0;
    if (!smem_set) {
        cudaFuncSetAttribute(rnn_kernel,
                             cudaFuncAttributeMaxDynamicSharedMemorySize, 163840);
        smem_set = 1;
    }

    xproj_kernel<<<dim3(8, Tt), 256>>>(x, W_ih0, b_ih0, b_hh0);
    rnn_kernel<<<G_CTAS, RNN_THREADS, 163840>>>(h0, W_hh0, W_ih1, b_ih1, W_hh1, b_hh1);
    head_kernel<<<Bb, Oo>>>(W_out, b_out, out);
}

// round 17
// speedup vs baseline: 1.0499x; 1.0499x over previous
#include <cuda_runtime.h>
#include <math.h>

// Problem dims
#define Tt 1024
#define Bb 64
#define Ii 256
#define Hh 512
#define Oo 128

// Scan grid: 128 CTAs. Group = 16 CTAs sharing 8 batches; each CTA owns 32 cols
// of BOTH layers. 8 independent groups.
#define G_CTAS 128
#define RNN_THREADS 256

// ---------------- device scratch (no runtime allocation allowed) ----------------
__device__ float g_xproj[(size_t)Tt * Bb * Hh];   // x@W_ih0^T + b_ih0 + b_hh0, [t][b][h]
__device__ float g_h0[4][Bb * Hh];                // quad-buffered layer-0 hidden
__device__ float g_h1[4][Bb * Hh];                // quad-buffered layer-1 hidden
__device__ unsigned g_flag0[G_CTAS * 32];         // L0 pipeline flags (128B padded)
__device__ unsigned g_flag1[G_CTAS * 32];         // L1 pipeline flags

// ---------------- packed f32x2 helpers ----------------
#define FMA2(acc, a, b) \
    asm("fma.rn.f32x2 %0, %1, %2, %0;" : "+l"(acc) : "l"(a), "l"(b))

__device__ __forceinline__ float f2sum(unsigned long long u) {
    float lo, hi;
    asm("mov.b64 {%0,%1}, %2;" : "=f"(lo), "=f"(hi) : "l"(u));
    return lo + hi;
}

// 16B L2-coherent global load as two packed f32x2 operands
__device__ __forceinline__ void ldcg2x64(const float* g,
                                         unsigned long long& a, unsigned long long& b) {
    asm volatile("ld.global.cg.v2.u64 {%0,%1}, [%2];" : "=l"(a), "=l"(b) : "l"(g));
}

__device__ __forceinline__ unsigned ld_acq(const unsigned* p) {
    unsigned v;
    asm volatile("ld.acquire.gpu.u32 %0, [%1];" : "=r"(v) : "l"(p) : "memory");
    return v;
}
// release store: publishes all writes HB-ordered before it (bar.sync provides HB)
__device__ __forceinline__ void st_release(unsigned* p, unsigned v) {
    asm volatile("st.release.gpu.u32 [%0], %1;" :: "l"(p), "r"(v) : "memory");
}
__device__ __forceinline__ void named_bar(int id) {
    asm volatile("bar.sync %0, 128;" :: "r"(id) : "memory");
}

// Multi-value butterfly allreduce: on return v[0] holds, for lane L, the full
// 32-lane sum of original v[L]. 31 shfls total.
__device__ __forceinline__ void butterfly32(float (&v)[32], int ln) {
    #pragma unroll
    for (int m = 16; m >= 1; m >>= 1) {
        #pragma unroll
        for (int i = 0; i < m; ++i) {
            float a = v[i], b = v[i + m];
            float send = (ln & m) ? a : b;
            float recv = __shfl_xor_sync(0xffffffffu, send, m);
            v[i] = (ln & m) ? (b + recv) : (a + recv);
        }
    }
}

// =================================================================================
// Kernel 1: xproj[t][b][j] = sum_i x[b][t][i] * W_ih0[j][i] + b_ih0[j] + b_hh0[j]
// =================================================================================
__global__ void __launch_bounds__(256) xproj_kernel(
    const float* __restrict__ x, const float* __restrict__ W,
    const float* __restrict__ bih, const float* __restrict__ bhh)
{
    __shared__ float xs[64 * 68];
    __shared__ float ws[64 * 68];

    const int t   = blockIdx.y;
    const int n0  = blockIdx.x * 64;
    const int tid = threadIdx.x;
    const int tx  = tid & 15;
    const int ty  = tid >> 4;
    const int mi0 = ty * 4;
    const int ni0 = tx * 4;

    float acc[4][4] = {};

    for (int kc = 0; kc < 4; ++kc) {
        const int k0 = kc * 64;
        for (int idx = tid; idx < 1024; idx += 256) {
            int b  = idx >> 4;
            int c4 = idx & 15;
            float4 v = *reinterpret_cast<const float4*>(
                x + ((size_t)b * Tt + t) * Ii + k0 + c4 * 4);
            *reinterpret_cast<float4*>(xs + b * 68 + c4 * 4) = v;
        }
        for (int idx = tid; idx < 1024; idx += 256) {
            int nl = idx >> 4;
            int c4 = idx & 15;
            float4 v = *reinterpret_cast<const float4*>(
                W + (size_t)(n0 + nl) * Ii + k0 + c4 * 4);
            int k = c4 * 4;
            ws[(k + 0) * 68 + nl] = v.x;
            ws[(k + 1) * 68 + nl] = v.y;
            ws[(k + 2) * 68 + nl] = v.z;
            ws[(k + 3) * 68 + nl] = v.w;
        }
        __syncthreads();
        #pragma unroll 8
        for (int k = 0; k < 64; ++k) {
            float4 wv = *reinterpret_cast<const float4*>(ws + k * 68 + ni0);
            float x0 = xs[(mi0 + 0) * 68 + k];
            float x1 = xs[(mi0 + 1) * 68 + k];
            float x2 = xs[(mi0 + 2) * 68 + k];
            float x3 = xs[(mi0 + 3) * 68 + k];
            acc[0][0] += x0 * wv.x; acc[0][1] += x0 * wv.y; acc[0][2] += x0 * wv.z; acc[0][3] += x0 * wv.w;
            acc[1][0] += x1 * wv.x; acc[1][1] += x1 * wv.y; acc[1][2] += x1 * wv.z; acc[1][3] += x1 * wv.w;
            acc[2][0] += x2 * wv.x; acc[2][1] += x2 * wv.y; acc[2][2] += x2 * wv.z; acc[2][3] += x2 * wv.w;
            acc[3][0] += x3 * wv.x; acc[3][1] += x3 * wv.y; acc[3][2] += x3 * wv.z; acc[3][3] += x3 * wv.w;
        }
        __syncthreads();
    }

    float4 bias;
    bias.x = bih[n0 + ni0 + 0] + bhh[n0 + ni0 + 0];
    bias.y = bih[n0 + ni0 + 1] + bhh[n0 + ni0 + 1];
    bias.z = bih[n0 + ni0 + 2] + bhh[n0 + ni0 + 2];
    bias.w = bih[n0 + ni0 + 3] + bhh[n0 + ni0 + 3];
    #pragma unroll
    for (int i = 0; i < 4; ++i) {
        float4 o;
        o.x = acc[i][0] + bias.x;
        o.y = acc[i][1] + bias.y;
        o.z = acc[i][2] + bias.z;
        o.w = acc[i][3] + bias.w;
        *reinterpret_cast<float4*>(
            g_xproj + ((size_t)t * Bb + (mi0 + i)) * Hh + n0 + ni0) = o;
    }
}

// =================================================================================
// Kernel 2: persistent scan, two decoupled pipelines, group = 16 CTAs / 8 batches.
//   L0 (warps 4-7, flags0): h0(p) = tanh(xproj[p-1] + h0(p-1)@W_hh0^T)
//   L1 (warps 0-3, flags1): h1(p) = tanh(h0(p)@W_ih1^T + h1(p-1)@W_hh1^T + b)
// BOTH pipelines read h directly from L2 (no smem staging) -> 2 named bars/step.
// Publish = bar + st.release.gpu (no membar.gl). Quad buffers give elasticity.
//   L0 polls: flags0 >= base0+p, flags1 >= base1+p-3 (slot safety, depth 4)
//   L1 polls: flags0 >= base0+1+p, flags1 >= base1+p
// =================================================================================
extern __shared__ float smf[];

__global__ void __launch_bounds__(RNN_THREADS, 1) rnn_kernel(
    const float* __restrict__ h_init,
    const float* __restrict__ W_hh0,
    const float* __restrict__ W_ih1, const float* __restrict__ b_ih1,
    const float* __restrict__ W_hh1, const float* __restrict__ b_hh1)
{
    const int tid = threadIdx.x;
    const int cta = blockIdx.x;
    const int ln  = tid & 31;
    const int wl  = (tid >> 5) & 3;      // warp index within half
    const bool isL0 = (tid >= 128);      // hi-wid warps: latency-critical h0 chain
    const int tpr = tid & 127;           // thread rank within half
    const int group = cta >> 4;          // 8 groups of 16 CTAs
    const int B0  = group * 8;           // 8 batches per group
    const int C0  = (cta & 15) * 32;     // 32 cols per CTA
    const int cw  = wl * 8;              // warp local col base (0/8/16/24)

    // SMEM: W0[32][512] | Wi1[32][512] | Wh1[32][512]  (192 KB, weights only)
    float* W0  = smf;
    float* Wi1 = smf + 16384;
    float* Wh1 = smf + 32768;

    const unsigned base0 = g_flag0[cta * 32];   // uniform across CTAs between launches
    const unsigned base1 = g_flag1[cta * 32];

    // ---- load weight slices (K contiguous per col) ----
    {
        float4* d0 = reinterpret_cast<float4*>(W0);
        float4* d1 = reinterpret_cast<float4*>(Wi1);
        float4* d2 = reinterpret_cast<float4*>(Wh1);
        for (int i = tid; i < 32 * 128; i += RNN_THREADS) {
            int c = i >> 7, k4 = i & 127;
            size_t go = (size_t)(C0 + c) * Hh + k4 * 4;
            d0[i] = *reinterpret_cast<const float4*>(W_hh0 + go);
            d1[i] = *reinterpret_cast<const float4*>(W_ih1 + go);
            d2[i] = *reinterpret_cast<const float4*>(W_hh1 + go);
        }
    }
    // ---- init state: 16 members split their group's 8x512 slice (slot 0) ----
    {
        float4* h0d = reinterpret_cast<float4*>(g_h0[0] + (size_t)B0 * Hh);
        float4* h1d = reinterpret_cast<float4*>(g_h1[0] + (size_t)B0 * Hh);
        const float4* s0 = reinterpret_cast<const float4*>(h_init + (size_t)B0 * Hh);
        const float4* s1 = reinterpret_cast<const float4*>(h_init + (size_t)(Bb + B0) * Hh);
        int mem = cta & 15;                        // 1024 float4 / 16 members = 64 each
        if (tid < 64) {
            int i = mem * 64 + tid;
            h0d[i] = s0[i];
            h1d[i] = s1[i];
        }
    }
    __syncthreads();
    if (tid == 0) {
        st_release(&g_flag0[cta * 32], base0 + 1);   // h0(0) visible
        st_release(&g_flag1[cta * 32], base1 + 1);   // h1(0) visible
    }

    // per-lane output mapping (flat acc idx = b*8+c): out0 b=ln>>3, out1 b=4+(ln>>3)
    const int ob0 = ln >> 3;             // batches 0..3
    const int ob1 = ob0 + 4;             // batches 4..7
    const int gc  = C0 + cw + (ln & 7);

    if (isL0) {
        // ================= L0 pipeline: warps 4-7, named barrier 1 =================
        const float* xpa = g_xproj + (size_t)(B0 + ob0) * Hh + gc;
        const float* xpb = g_xproj + (size_t)(B0 + ob1) * Hh + gc;

        for (int p = 1; p <= Tt; ++p) {
            if (tpr < 16) {
                const unsigned* f0 = &g_flag0[(group * 16 + tpr) * 32];
                const unsigned* f1 = &g_flag1[(group * 16 + tpr) * 32];
                unsigned t0 = base0 + p;          // h0(p-1) ready everywhere
                unsigned t1 = base1 + p - 3;      // L1 done step p-4 (slot p&3 safe)
                while ((int)(ld_acq(f0) - t0) < 0 || (int)(ld_acq(f1) - t1) < 0) { }
            }
            named_bar(1);

            const float* h0prev = g_h0[(p - 1) & 3];
            float*       h0out  = g_h0[p & 3];

            const size_t toff = (size_t)(p - 1) * (Bb * Hh);
            float px0 = __ldcg(xpa + toff);
            float px1 = __ldcg(xpb + toff);

            unsigned long long acc[64];
            #pragma unroll
            for (int i = 0; i < 64; ++i) acc[i] = 0ull;

            #pragma unroll
            for (int m = 0; m < 4; ++m) {
                const int k = m * 128 + ln * 4;
                unsigned long long hx[8], hy[8];
                #pragma unroll
                for (int b = 0; b < 8; ++b)
                    ldcg2x64(h0prev + (size_t)(B0 + b) * Hh + k, hx[b], hy[b]);
                #pragma unroll
                for (int c = 0; c < 8; ++c) {
                    ulonglong2 w2 = *reinterpret_cast<const ulonglong2*>(W0 + (cw + c) * 512 + k);
                    #pragma unroll
                    for (int b = 0; b < 8; ++b) {
                        FMA2(acc[b * 8 + c], hx[b], w2.x);
                        FMA2(acc[b * 8 + c], hy[b], w2.y);
                    }
                }
            }

            float v[32];
            #pragma unroll
            for (int i = 0; i < 32; ++i) v[i] = f2sum(acc[i]);
            butterfly32(v, ln);
            float out0 = v[0];
            #pragma unroll
            for (int i = 0; i < 32; ++i) v[i] = f2sum(acc[32 + i]);
            butterfly32(v, ln);
            float out1 = v[0];

            h0out[(size_t)(B0 + ob0) * Hh + gc] = tanhf(out0 + px0);
            h0out[(size_t)(B0 + ob1) * Hh + gc] = tanhf(out1 + px1);

            named_bar(1);
            if (tpr == 0)
                st_release(&g_flag0[cta * 32], base0 + 1 + p);
        }
    } else {
        // ================= L1 pipeline: warps 0-3, named barrier 2 =================
        const float bias1 = b_ih1[gc] + b_hh1[gc];

        for (int p = 1; p <= Tt; ++p) {
            if (tpr < 16) {
                const unsigned* f0 = &g_flag0[(group * 16 + tpr) * 32];
                const unsigned* f1 = &g_flag1[(group * 16 + tpr) * 32];
                unsigned t0 = base0 + 1 + p;    // h0(p) ready
                unsigned t1 = base1 + p;        // h1(p-1) ready (+ slot safety)
                while ((int)(ld_acq(f0) - t0) < 0 || (int)(ld_acq(f1) - t1) < 0) { }
            }
            named_bar(2);

            const float* h0cur  = g_h0[p & 3];         // h0(p)
            const float* h1prev = g_h1[(p - 1) & 3];   // h1(p-1)
            float*       h1out  = g_h1[p & 3];         // h1(p)

            unsigned long long acc[64];
            #pragma unroll
            for (int i = 0; i < 64; ++i) acc[i] = 0ull;

            #pragma unroll
            for (int m = 0; m < 8; ++m) {
                const float* hsrc = (m < 4) ? h0cur : h1prev;
                const float* Wa   = (m < 4) ? Wi1 : Wh1;
                const int k = (m & 3) * 128 + ln * 4;
                unsigned long long hx[8], hy[8];
                #pragma unroll
                for (int b = 0; b < 8; ++b)
                    ldcg2x64(hsrc + (size_t)(B0 + b) * Hh + k, hx[b], hy[b]);
                #pragma unroll
                for (int c = 0; c < 8; ++c) {
                    ulonglong2 w2 = *reinterpret_cast<const ulonglong2*>(Wa + (cw + c) * 512 + k);
                    #pragma unroll
                    for (int b = 0; b < 8; ++b) {
                        FMA2(acc[b * 8 + c], hx[b], w2.x);
                        FMA2(acc[b * 8 + c], hy[b], w2.y);
                    }
                }
            }

            float v[32];
            #pragma unroll
            for (int i = 0; i < 32; ++i) v[i] = f2sum(acc[i]);
            butterfly32(v, ln);
            float out0 = v[0];
            #pragma unroll
            for (int i = 0; i < 32; ++i) v[i] = f2sum(acc[32 + i]);
            butterfly32(v, ln);
            float out1 = v[0];

            h1out[(size_t)(B0 + ob0) * Hh + gc] = tanhf(out0 + bias1);
            h1out[(size_t)(B0 + ob1) * Hh + gc] = tanhf(out1 + bias1);

            named_bar(2);
            if (tpr == 0)
                st_release(&g_flag1[cta * 32], base1 + 1 + p);
        }
    }
}

// =================================================================================
// Kernel 3: out[b][o] = h1(1024)[b] . W_out[o] + b_out[o]   (1024 & 3 == slot 0)
// =================================================================================
__global__ void __launch_bounds__(128) head_kernel(
    const float* __restrict__ W_out, const float* __restrict__ b_out,
    float* __restrict__ out)
{
    const int b = blockIdx.x;
    const int o = threadIdx.x;
    const float* h = g_h1[0] + b * Hh;
    const float* wv = W_out + (size_t)o * Hh;
    float acc = 0.f;
    #pragma unroll 8
    for (int k = 0; k < Hh; k += 4) {
        float4 hv = *reinterpret_cast<const float4*>(h + k);
        float4 wr = *reinterpret_cast<const float4*>(wv + k);
        acc += hv.x * wr.x + hv.y * wr.y + hv.z * wr.z + hv.w * wr.w;
    }
    out[b * Oo + o] = acc + b_out[o];
}

// =================================================================================
extern "C" void kernel_launch(void* const* d_in, const int* in_sizes, int n_in,
                              void* d_out, int out_size)
{
    (void)in_sizes; (void)n_in; (void)out_size;
    const float* x      = (const float*)d_in[0];
    const float* h0     = (const float*)d_in[1];
    const float* W_ih0  = (const float*)d_in[2];
    const float* b_ih0  = (const float*)d_in[3];
    const float* W_hh0  = (const float*)d_in[4];
    const float* b_hh0  = (const float*)d_in[5];
    const float* W_ih1  = (const float*)d_in[6];
    const float* b_ih1  = (const float*)d_in[7];
    const float* W_hh1  = (const float*)d_in[8];
    const float* b_hh1  = (const float*)d_in[9];
    const float* W_out  = (const float*)d_in[10];
    const float* b_out  = (const float*)d_in[11];
    float* out = (float*)d_out;

    // SMEM: 3 x (32x512 floats) = 49152 floats = 192 KB (weights only)
    static int smem_set = 0;
    if (!smem_set) {
        cudaFuncSetAttribute(rnn_kernel,
                             cudaFuncAttributeMaxDynamicSharedMemorySize, 196608);
        smem_set = 1;
    }

    xproj_kernel<<<dim3(8, Tt), 256>>>(x, W_ih0, b_ih0, b_hh0);
    rnn_kernel<<<G_CTAS, RNN_THREADS, 196608>>>(h0, W_hh0, W_ih1, b_ih1, W_hh1, b_hh1);
    head_kernel<<<Bb, Oo>>>(W_out, b_out, out);
}